// round 17
// baseline (speedup 1.0000x reference)
#include <cuda_runtime.h>
#include <cuda_bf16.h>
#include <cuda_fp16.h>
#include <math.h>
#include <stdint.h>

// Problem constants
#define T_SEQ 2048
#define C_DIM 2048
#define NHQ   16
#define NHKV  4
#define HD    128

// ---------------------------------------------------------------------------
// Helpers
// ---------------------------------------------------------------------------
__device__ __forceinline__ uint32_t smem_u32(const void* p) {
    uint32_t a;
    asm("{ .reg .u64 t; cvta.to.shared.u64 t, %1; cvt.u32.u64 %0, t; }" : "=r"(a) : "l"(p));
    return a;
}

__device__ __forceinline__ void ldmx4(uint32_t* r, uint32_t addr) {
    asm volatile("ldmatrix.sync.aligned.m8n8.x4.shared.b16 {%0,%1,%2,%3}, [%4];"
                 : "=r"(r[0]), "=r"(r[1]), "=r"(r[2]), "=r"(r[3]) : "r"(addr));
}

__device__ __forceinline__ void mma_f16m(float* c, const uint32_t* a, uint32_t b0, uint32_t b1) {
    asm volatile(
        "mma.sync.aligned.m16n8k16.row.col.f32.f16.f16.f32 "
        "{%0,%1,%2,%3}, {%4,%5,%6,%7}, {%8,%9}, {%0,%1,%2,%3};"
        : "+f"(c[0]), "+f"(c[1]), "+f"(c[2]), "+f"(c[3])
        : "r"(a[0]), "r"(a[1]), "r"(a[2]), "r"(a[3]), "r"(b0), "r"(b1));
}

#define CP_ASYNC16(saddr, gptr) \
    asm volatile("cp.async.cg.shared.global [%0], [%1], 16;" :: "r"(saddr), "l"(gptr) : "memory")
#define CP_COMMIT() asm volatile("cp.async.commit_group;" ::: "memory")
#define CP_WAIT(n)  asm volatile("cp.async.wait_group %0;" :: "n"(n) : "memory")

__device__ __forceinline__ uint32_t pack_f16(float x0, float x1) {
    __half2 h = __floats2half2_rn(x0, x1);
    return *reinterpret_cast<uint32_t*>(&h);
}

// ---------------------------------------------------------------------------
// Scratch (all-fp16; no fp32 intermediates)
// ---------------------------------------------------------------------------
__device__ __half g_xf[T_SEQ * C_DIM];
__device__ __half g_WqTf[C_DIM * C_DIM];
__device__ __half g_WkTf[512 * C_DIM];
__device__ __half g_WvTf[512 * C_DIM];
__device__ __half g_WoTf[C_DIM * C_DIM];
__device__ __half g_Qf[T_SEQ * C_DIM];
__device__ __half g_Kf[T_SEQ * 512];
__device__ __half g_Vtf[512 * T_SEQ];
__device__ __half g_Of[T_SEQ * C_DIM];

// ---------------------------------------------------------------------------
// fp16 GEMM core: acc(fp32) = A @ B^T. 128x128 tile, BK=32, 3-stage ring
// (rotating stage pointers), lookahead 2, one barrier/chunk.
// 80B padded rows. SMEM = 61440 B -> 3 CTAs/SM.
// ---------------------------------------------------------------------------
#define TILE_B   10240          // 128 rows * 80 bytes
#define G_STAGES 3
#define GEMM_SMEM_BYTES (G_STAGES * 2 * TILE_B)   // 61440

__device__ __forceinline__ void gemm_core(
    const char* A, const char* B, int lda, int ldb, int m0, int n0, int nch,
    float acc[2][8][4])
{
    extern __shared__ char smem[];
    const uint32_t sb = smem_u32(smem);
    const int tid = threadIdx.x;
    const int warp = tid >> 5, lane = tid & 31;
    const int wm = warp & 3, wn = warp >> 2;

    auto load1 = [&](const char* G, int ld, int r0, int k0, uint32_t tbase) {
#pragma unroll
        for (int i = 0; i < 2; i++) {
            int idx = tid + i * 256;
            int row = idx >> 2, ch = idx & 3;
            const char* g = G + ((long long)(r0 + row) * ld + k0) * 2 + ch * 16;
            CP_ASYNC16(tbase + row * 80 + ch * 16, g);
        }
    };

    auto issue = [&](int c, uint32_t st) {
        const int k0 = c * 32;
        load1(A, lda, m0, k0, st);
        load1(B, ldb, n0, k0, st + TILE_B);
        CP_COMMIT();
    };

#pragma unroll
    for (int i = 0; i < 2; i++)
#pragma unroll
        for (int j = 0; j < 8; j++)
#pragma unroll
            for (int q = 0; q < 4; q++) acc[i][j][q] = 0.f;

    uint32_t st0 = sb, st1 = sb + 2 * TILE_B, st2 = sb + 4 * TILE_B;

    // prologue: 2 chunks in flight
    issue(0, st0);
    if (nch > 1) issue(1, st1); else CP_COMMIT();

    const uint32_t lmOff = (uint32_t)((lane & 15) * 80 + ((lane & 16) ? 16 : 0));

    for (int c = 0; c < nch; ++c) {
        CP_WAIT(1);
        __syncthreads();
        // barrier proves chunk c visible AND all warps done with chunk c-1,
        // whose stage is st2 -> safe to refill.
        if (c + 2 < nch) issue(c + 2, st2); else CP_COMMIT();

#pragma unroll
        for (int ks = 0; ks < 32; ks += 16) {
            uint32_t aF[2][4], bF[4][4];
#pragma unroll
            for (int mt = 0; mt < 2; mt++)
                ldmx4(aF[mt], st0 + (wm * 32 + mt * 16) * 80 + ks * 2 + lmOff);
#pragma unroll
            for (int g = 0; g < 4; g++)
                ldmx4(bF[g], st0 + TILE_B + (wn * 64 + g * 16) * 80 + ks * 2 + lmOff);

#pragma unroll
            for (int mt = 0; mt < 2; mt++)
#pragma unroll
                for (int g = 0; g < 4; g++) {
                    mma_f16m(acc[mt][2 * g + 0], aF[mt], bF[g][0], bF[g][2]);
                    mma_f16m(acc[mt][2 * g + 1], aF[mt], bF[g][1], bF[g][3]);
                }
        }
        // rotate ring
        uint32_t t = st0; st0 = st1; st1 = st2; st2 = t;
    }
    __syncthreads();
}

// ---------------------------------------------------------------------------
// Merged Q/K/V projection with fused RoPE + transpose epilogue.
// ---------------------------------------------------------------------------
#define STG_PITCH 136   // halves per staged row (272 B)

__global__ void __launch_bounds__(256, 3) qkv_proj_kernel(
    const __half* __restrict__ xf,
    const __half* __restrict__ WqTf, const __half* __restrict__ WkTf,
    const __half* __restrict__ WvTf,
    __half* __restrict__ Qf, __half* __restrict__ Kf, __half* __restrict__ Vtf)
{
    const int bn = blockIdx.x, bm = blockIdx.y;
    const int m0 = bm * 128;

    const __half* W;
    if (bn < 16)      W = WqTf + (size_t)bn * 128 * C_DIM;
    else if (bn < 20) W = WkTf + (size_t)(bn - 16) * 128 * C_DIM;
    else              W = WvTf + (size_t)(bn - 20) * 128 * C_DIM;

    float acc[2][8][4];
    gemm_core((const char*)xf, (const char*)W, C_DIM, C_DIM, m0, 0, 64, acc);

    extern __shared__ char smem[];
    __half* stg = (__half*)smem;
    const int tid = threadIdx.x, warp = tid >> 5, lane = tid & 31;
    const int wm = warp & 3, wn = warp >> 2;
    const int r0 = wm * 32 + (lane >> 2);
    const int c0 = wn * 64 + (lane & 3) * 2;
#pragma unroll
    for (int mt = 0; mt < 2; mt++)
#pragma unroll
        for (int nt = 0; nt < 8; nt++) {
            int r = r0 + mt * 16, c = c0 + nt * 8;
            *(uint32_t*)&stg[r * STG_PITCH + c]       = pack_f16(acc[mt][nt][0], acc[mt][nt][1]);
            *(uint32_t*)&stg[(r + 8) * STG_PITCH + c] = pack_f16(acc[mt][nt][2], acc[mt][nt][3]);
        }
    __syncthreads();

    if (bn < 20) {
        __half* outp; int ldo, head;
        if (bn < 16) { outp = Qf; ldo = C_DIM; head = bn; }
        else         { outp = Kf; ldo = 512;   head = bn - 16; }
        const int d  = tid & 63;
        const int rb = tid >> 6;
        const float freq = __expf(-(float)d * 0.14391156831f);  // 10000^{-d/64}
#pragma unroll 4
        for (int i = 0; i < 32; i++) {
            int row = rb * 32 + i;
            int s = m0 + row;
            float sn, cs;
            sincosf((float)s * freq, &sn, &cs);
            float v0 = __half2float(stg[row * STG_PITCH + d]);
            float v1 = __half2float(stg[row * STG_PITCH + d + 64]);
            size_t o = (size_t)s * ldo + head * HD + d;
            outp[o]      = __float2half_rn(v0 * cs - v1 * sn);
            outp[o + 64] = __float2half_rn(v1 * cs + v0 * sn);
        }
    } else {
        const int head = bn - 20;
        const int col = tid & 127, half = tid >> 7;
        __half* vrow = Vtf + (size_t)(head * HD + col) * T_SEQ + m0 + half * 64;
#pragma unroll
        for (int rb = 0; rb < 8; rb++) {
            __half tmp[8];
#pragma unroll
            for (int r = 0; r < 8; r++)
                tmp[r] = stg[(half * 64 + rb * 8 + r) * STG_PITCH + col];
            *(uint4*)&vrow[rb * 8] = *(uint4*)tmp;
        }
    }
}

// ---------------------------------------------------------------------------
// Output projection
// ---------------------------------------------------------------------------
__global__ void __launch_bounds__(256, 3) out_proj_kernel(
    const __half* __restrict__ Of, const __half* __restrict__ WoTf,
    float* __restrict__ out)
{
    const int m0 = blockIdx.y * 128, n0 = blockIdx.x * 128;
    float acc[2][8][4];
    gemm_core((const char*)Of, (const char*)WoTf, C_DIM, C_DIM, m0, n0, 64, acc);

    const int tid = threadIdx.x, warp = tid >> 5, lane = tid & 31;
    const int wm = warp & 3, wn = warp >> 2;
    const int cRow = m0 + wm * 32 + (lane >> 2);
    const int cCol = n0 + wn * 64 + (lane & 3) * 2;
#pragma unroll
    for (int mt = 0; mt < 2; mt++) {
#pragma unroll
        for (int nt = 0; nt < 8; nt++) {
            float* p0 = out + (long long)(cRow + mt * 16) * C_DIM + cCol + nt * 8;
            float* p1 = p0 + 8LL * C_DIM;
            *(float2*)p0 = make_float2(acc[mt][nt][0], acc[mt][nt][1]);
            *(float2*)p1 = make_float2(acc[mt][nt][2], acc[mt][nt][3]);
        }
    }
}

// ---------------------------------------------------------------------------
// Fused flash attention. Softcap via odd polynomial; single barrier per chunk.
// (Unchanged from R16.)
// ---------------------------------------------------------------------------
#define FA_STAGES     4
#define FA_CHUNK_B    10240
#define FA_QROW_B     272
#define FA_Q_B        (128 * FA_QROW_B)
#define FA_SMEM_BYTES (FA_Q_B + FA_STAGES * FA_CHUNK_B)   // 75776

__global__ void __launch_bounds__(256) flash_attn_kernel(
    const __half* __restrict__ Qf, const __half* __restrict__ Kf,
    const __half* __restrict__ Vtf,
    __half* __restrict__ Of)
{
    const int bm  = 15 - blockIdx.y;
    const int h   = blockIdx.x;
    const int kvh = h & 3;
    const int nkt = bm + 1;
    const int nchunks = nkt * 8;

    const int tid = threadIdx.x, warp = tid >> 5, lane = tid & 31;

    extern __shared__ char smem[];
    const uint32_t sb   = smem_u32(smem);
    const uint32_t qf_s = sb;
    const uint32_t stg  = sb + FA_Q_B;

    {
#pragma unroll
        for (int i = 0; i < 8; i++) {
            int idx = tid + i * 256;
            int row = idx >> 4, ch = idx & 15;
            const char* g = (const char*)(Qf + (size_t)(bm * 128 + row) * C_DIM + h * HD) + ch * 16;
            CP_ASYNC16(qf_s + row * FA_QROW_B + ch * 16, g);
        }
        CP_COMMIT();
    }

    auto issueChunk = [&](int q) {
        const int kt = q >> 3, ph = q & 7;
        const uint32_t st = stg + (uint32_t)(q & (FA_STAGES - 1)) * FA_CHUNK_B;
        const char* G;
        long long rowBase; int ld, colBase;
        if (ph < 4) {
            G = (const char*)Kf; ld = 512;
            rowBase = (long long)kt * 128;
            colBase = kvh * HD + ph * 32;
        } else {
            G = (const char*)Vtf; ld = T_SEQ;
            rowBase = (long long)kvh * HD;
            colBase = kt * 128 + (ph - 4) * 32;
        }
#pragma unroll
        for (int i = 0; i < 2; i++) {
            int idx = tid + i * 256;
            int row = idx >> 2, ch = idx & 3;
            const char* g = G + ((rowBase + row) * ld + colBase) * 2 + ch * 16;
            CP_ASYNC16(st + row * 80 + ch * 16, g);
        }
        CP_COMMIT();
    };

    issueChunk(0);
    if (nchunks > 1) issueChunk(1); else CP_COMMIT();
    if (nchunks > 2) issueChunk(2); else CP_COMMIT();

    CP_WAIT(3);
    __syncthreads();
    const uint32_t lmQ  = (uint32_t)((lane & 15) * FA_QROW_B + ((lane & 16) ? 16 : 0));
    const uint32_t lm80 = (uint32_t)((lane & 15) * 80 + ((lane & 16) ? 16 : 0));
    uint32_t qfrag[8][4];
#pragma unroll
    for (int kc = 0; kc < 8; kc++)
        ldmx4(qfrag[kc], qf_s + (warp * 16) * FA_QROW_B + kc * 32 + lmQ);

    float oacc[16][4];
#pragma unroll
    for (int g = 0; g < 16; g++)
#pragma unroll
        for (int e = 0; e < 4; e++) oacc[g][e] = 0.f;
    float mrow[2] = {-1e30f, -1e30f};
    float lrow[2] = {0.f, 0.f};

    // z = 50*tanh(s*A), |x| small -> odd polynomial exact to <1e-5
    const float Acap = 0.08838834764831845f / 50.f;
    uint32_t pf[8][4];

    for (int kt = 0; kt < nkt; kt++) {
        float sacc[16][4];
#pragma unroll
        for (int g = 0; g < 16; g++)
#pragma unroll
            for (int e = 0; e < 4; e++) sacc[g][e] = 0.f;

        // ---- S phase ----
        for (int dc = 0; dc < 4; dc++) {
            const int q = kt * 8 + dc;
            CP_WAIT(2);
            __syncthreads();
            if (q + 3 < nchunks) issueChunk(q + 3);
            const uint32_t st = stg + (uint32_t)(q & (FA_STAGES - 1)) * FA_CHUNK_B;
#pragma unroll
            for (int c2 = 0; c2 < 2; c2++) {
                const int kc = dc * 2 + c2;
#pragma unroll
                for (int g = 0; g < 8; g++) {
                    uint32_t kf[4];
                    ldmx4(kf, st + (g * 16) * 80 + c2 * 32 + lm80);
                    mma_f16m(sacc[2 * g],     qfrag[kc], kf[0], kf[2]);
                    mma_f16m(sacc[2 * g + 1], qfrag[kc], kf[1], kf[3]);
                }
            }
        }

        // ---- softcap (polynomial) + online softmax ----
        const bool diag = (kt == bm);
        const int rowLoc = warp * 16 + (lane >> 2);
        float zmax[2] = {-1e30f, -1e30f};
#pragma unroll
        for (int g = 0; g < 16; g++) {
#pragma unroll
            for (int e = 0; e < 4; e++) {
                float x = sacc[g][e] * Acap;
                float x2 = x * x;
                float z = 50.f * x * (1.f + x2 * (-0.333333333f + x2 * 0.133333333f));
                if (diag) {
                    int col = g * 8 + (lane & 3) * 2 + (e & 1);
                    int row = rowLoc + ((e >> 1) ? 8 : 0);
                    if (col > row) z = -1e30f;
                }
                sacc[g][e] = z;
                int r = e >> 1;
                zmax[r] = fmaxf(zmax[r], z);
            }
        }
#pragma unroll
        for (int o = 1; o <= 2; o <<= 1) {
            zmax[0] = fmaxf(zmax[0], __shfl_xor_sync(0xffffffffu, zmax[0], o));
            zmax[1] = fmaxf(zmax[1], __shfl_xor_sync(0xffffffffu, zmax[1], o));
        }
        float mnew[2] = {fmaxf(mrow[0], zmax[0]), fmaxf(mrow[1], zmax[1])};
        float alpha[2] = {__expf(mrow[0] - mnew[0]), __expf(mrow[1] - mnew[1])};
        float psum[2] = {0.f, 0.f};
#pragma unroll
        for (int g = 0; g < 16; g++) {
#pragma unroll
            for (int e = 0; e < 4; e++) {
                int r = e >> 1;
                float p = __expf(sacc[g][e] - mnew[r]);
                sacc[g][e] = p;
                psum[r] += p;
            }
        }
#pragma unroll
        for (int o = 1; o <= 2; o <<= 1) {
            psum[0] += __shfl_xor_sync(0xffffffffu, psum[0], o);
            psum[1] += __shfl_xor_sync(0xffffffffu, psum[1], o);
        }
        lrow[0] = lrow[0] * alpha[0] + psum[0];
        lrow[1] = lrow[1] * alpha[1] + psum[1];
        mrow[0] = mnew[0]; mrow[1] = mnew[1];
#pragma unroll
        for (int g = 0; g < 16; g++) {
            oacc[g][0] *= alpha[0]; oacc[g][1] *= alpha[0];
            oacc[g][2] *= alpha[1]; oacc[g][3] *= alpha[1];
        }
#pragma unroll
        for (int k16 = 0; k16 < 8; k16++) {
            const int g0 = 2 * k16, g1 = g0 + 1;
            pf[k16][0] = pack_f16(sacc[g0][0], sacc[g0][1]);
            pf[k16][1] = pack_f16(sacc[g0][2], sacc[g0][3]);
            pf[k16][2] = pack_f16(sacc[g1][0], sacc[g1][1]);
            pf[k16][3] = pack_f16(sacc[g1][2], sacc[g1][3]);
        }

        // ---- PV phase ----
        for (int tc = 0; tc < 4; tc++) {
            const int q = kt * 8 + 4 + tc;
            CP_WAIT(2);
            __syncthreads();
            if (q + 3 < nchunks) issueChunk(q + 3);
            const uint32_t st = stg + (uint32_t)(q & (FA_STAGES - 1)) * FA_CHUNK_B;
#pragma unroll
            for (int c2 = 0; c2 < 2; c2++) {
                const int k16 = tc * 2 + c2;
#pragma unroll
                for (int g = 0; g < 8; g++) {
                    uint32_t vh[4];
                    ldmx4(vh, st + (g * 16) * 80 + c2 * 32 + lm80);
                    mma_f16m(oacc[2 * g],     pf[k16], vh[0], vh[2]);
                    mma_f16m(oacc[2 * g + 1], pf[k16], vh[1], vh[3]);
                }
            }
        }
    }

    // ---- epilogue ----
    const float inv0 = 1.f / lrow[0];
    const float inv1 = 1.f / lrow[1];
    const int row0 = bm * 128 + warp * 16 + (lane >> 2);
    const int row1 = row0 + 8;
#pragma unroll
    for (int g = 0; g < 16; g++) {
        const int col = h * HD + g * 8 + (lane & 3) * 2;
        *(uint32_t*)(Of + (size_t)row0 * C_DIM + col) =
            pack_f16(oacc[g][0] * inv0, oacc[g][1] * inv0);
        *(uint32_t*)(Of + (size_t)row1 * C_DIM + col) =
            pack_f16(oacc[g][2] * inv1, oacc[g][3] * inv1);
    }
}

// ---------------------------------------------------------------------------
// Merged prep
// ---------------------------------------------------------------------------
__global__ void prep_kernel(
    const float* __restrict__ x,
    const float* __restrict__ wq, const float* __restrict__ wk,
    const float* __restrict__ wv, const float* __restrict__ wo,
    __half* __restrict__ xf,
    __half* __restrict__ WqTf, __half* __restrict__ WkTf,
    __half* __restrict__ WvTf, __half* __restrict__ WoTf)
{
    const int job = blockIdx.z;
    const int c0 = blockIdx.x * 32, r0 = blockIdx.y * 32;

    if (job == 4) {
#pragma unroll
        for (int j = 0; j < 32; j += 8) {
            size_t o = (size_t)(r0 + threadIdx.y + j) * C_DIM + c0 + threadIdx.x;
            xf[o] = __float2half_rn(x[o]);
        }
        return;
    }

    const float* src; __half* dst; int R, Cn;
    if (job == 0)      { src = wq; dst = WqTf; R = C_DIM; Cn = C_DIM; }
    else if (job == 1) { src = wk; dst = WkTf; R = C_DIM; Cn = 512; }
    else if (job == 2) { src = wv; dst = WvTf; R = C_DIM; Cn = 512; }
    else               { src = wo; dst = WoTf; R = C_DIM; Cn = C_DIM; }
    if (c0 >= Cn) return;

    __shared__ float t[32][33];
#pragma unroll
    for (int j = 0; j < 32; j += 8)
        t[threadIdx.y + j][threadIdx.x] =
            src[(size_t)(r0 + threadIdx.y + j) * Cn + c0 + threadIdx.x];
    __syncthreads();
#pragma unroll
    for (int j = 0; j < 32; j += 8) {
        float v = t[threadIdx.x][threadIdx.y + j];
        dst[(size_t)(c0 + threadIdx.y + j) * R + r0 + threadIdx.x] = __float2half_rn(v);
    }
}

// ---------------------------------------------------------------------------
// kernel_launch: 4 launches total.
// ---------------------------------------------------------------------------
extern "C" void kernel_launch(void* const* d_in, const int* in_sizes, int n_in,
                              void* d_out, int out_size)
{
    const float* x  = (const float*)d_in[0];
    const float* wq = (const float*)d_in[2];
    const float* wk = (const float*)d_in[3];
    const float* wv = (const float*)d_in[4];
    const float* wo = (const float*)d_in[5];
    float* out = (float*)d_out;

    cudaFuncSetAttribute(qkv_proj_kernel,
                         cudaFuncAttributeMaxDynamicSharedMemorySize, GEMM_SMEM_BYTES);
    cudaFuncSetAttribute(out_proj_kernel,
                         cudaFuncAttributeMaxDynamicSharedMemorySize, GEMM_SMEM_BYTES);
    cudaFuncSetAttribute(flash_attn_kernel,
                         cudaFuncAttributeMaxDynamicSharedMemorySize, FA_SMEM_BYTES);

    __half *xf, *WqTf, *WkTf, *WvTf, *WoTf, *Qf, *Kf, *Vtf, *Of;
    cudaGetSymbolAddress((void**)&xf, g_xf);
    cudaGetSymbolAddress((void**)&WqTf, g_WqTf);
    cudaGetSymbolAddress((void**)&WkTf, g_WkTf);
    cudaGetSymbolAddress((void**)&WvTf, g_WvTf);
    cudaGetSymbolAddress((void**)&WoTf, g_WoTf);
    cudaGetSymbolAddress((void**)&Qf, g_Qf);
    cudaGetSymbolAddress((void**)&Kf, g_Kf);
    cudaGetSymbolAddress((void**)&Vtf, g_Vtf);
    cudaGetSymbolAddress((void**)&Of, g_Of);

    // 1. merged prep
    prep_kernel<<<dim3(64, 64, 5), dim3(32, 8)>>>(
        x, wq, wk, wv, wo, xf, WqTf, WkTf, WvTf, WoTf);

    // 2. merged QKV projection with fused RoPE / V-transpose
    qkv_proj_kernel<<<dim3(24, 16), 256, GEMM_SMEM_BYTES>>>(
        xf, WqTf, WkTf, WvTf, Qf, Kf, Vtf);

    // 3. fused flash attention
    flash_attn_kernel<<<dim3(NHQ, 16), 256, FA_SMEM_BYTES>>>(Qf, Kf, Vtf, Of);

    // 4. out = Of @ WoTf^T
    out_proj_kernel<<<dim3(16, 16), 256, GEMM_SMEM_BYTES>>>(Of, WoTf, out);
}